// round 4
// baseline (speedup 1.0000x reference)
#include <cuda_runtime.h>
#include <math.h>

// Problem constants
#define T_ 256
#define B_ 64
#define P_ 1024
#define H_ 512

#define DECAY 0.999f

// Step-kernel tiling
#define RPB 64                 // pat rows per block
#define NWARP 8                // warps per block (256 threads)
#define RPW (RPB / NWARP)      // 8 rows per warp
#define BPB (P_ / RPB)         // 16 blocks per batch
#define NBLK (B_ * BPB)        // 1024 blocks per step

// Persistent state (static __device__ scratch — no runtime allocation)
__device__ float g_pat[(size_t)B_ * P_ * H_];   // 128 MB carried pattern state
__device__ float g_raw[2][B_ * P_];             // double-buffered pattern responses

// ---------------------------------------------------------------------------
// raw0: raw[b,p] = pat_in[b,p,:] . x[0,b,:]   (one warp per row)
// ---------------------------------------------------------------------------
__global__ __launch_bounds__(256) void raw0_kernel(const float* __restrict__ x,
                                                   const float* __restrict__ pat) {
    int gw = (blockIdx.x * 256 + threadIdx.x) >> 5;   // global warp = row id
    int lane = threadIdx.x & 31;
    int b = gw >> 10;           // /P_
    int p = gw & (P_ - 1);
    const float* row = pat + ((size_t)b * P_ + p) * H_;
    const float* xb = x + (size_t)b * H_;             // t = 0
    float d = 0.f;
#pragma unroll
    for (int j = 0; j < 4; j++) {
        int h = j * 128 + lane * 4;
        float4 o = *reinterpret_cast<const float4*>(row + h);
        float4 xv = *reinterpret_cast<const float4*>(xb + h);
        d += o.x * xv.x + o.y * xv.y + o.z * xv.z + o.w * xv.w;
    }
#pragma unroll
    for (int off = 16; off; off >>= 1) d += __shfl_xor_sync(0xffffffffu, d, off);
    if (lane == 0) g_raw[0][b * P_ + p] = d;
}

// ---------------------------------------------------------------------------
// One recurrence step, fully fused:
//   - per-block recompute of softmax stats from raw[b,:] (L2-resident, bitwise
//     identical across blocks of the same b)
//   - per row: pr, new_h accumulation (old pat), pat update + L2 normalize,
//     and raw_{t+1} = new_row . x_{t+1} computed from registers
//   - block-reduced new_h partials atomically added into out[t,b,:]
// Block order reverses on odd t so each step's pat read hits the lines the
// previous step wrote last (L2 ping-pong; pat ~ L2 capacity).
// ---------------------------------------------------------------------------
__global__ __launch_bounds__(256) void step_kernel(const float* __restrict__ x,
                                                   const float* __restrict__ pat_in,
                                                   float* __restrict__ out, int t) {
    __shared__ float s_red[256];
    __shared__ float s_acc[NWARP * H_];   // per-warp new_h partials (16 KB)

    int bid = blockIdx.x;
    if (t & 1) bid = NBLK - 1 - bid;      // alternate traversal direction
    int b = bid / BPB;
    int pblk = bid % BPB;
    int tid = threadIdx.x;
    int warp = tid >> 5, lane = tid & 31;

    const float* rawv = g_raw[t & 1] + b * P_;

    // ---- max over raw[b,:] ----
    float lm = -1e30f;
    for (int i = tid; i < P_; i += 256) lm = fmaxf(lm, rawv[i]);
    s_red[tid] = lm;
    __syncthreads();
    for (int s = 128; s > 0; s >>= 1) {
        if (tid < s) s_red[tid] = fmaxf(s_red[tid], s_red[tid + s]);
        __syncthreads();
    }
    float m = s_red[0];
    float thr = 0.9f * m;
    float sc = 10.f / m;
    __syncthreads();

    // ---- softmax denominator: sum exp(logit - 10) ----
    float ls = 0.f;
    for (int i = tid; i < P_; i += 256) {
        float r = rawv[i];
        float logit = (r >= thr) ? r * sc : 0.f;
        ls += __expf(logit - 10.f);
    }
    s_red[tid] = ls;
    __syncthreads();
    for (int s = 128; s > 0; s >>= 1) {
        if (tid < s) s_red[tid] += s_red[tid + s];
        __syncthreads();
    }
    float invden = 1.f / s_red[0];

    // ---- main per-row work ----
    const float* src = (t == 0) ? pat_in : (const float*)g_pat;
    const float* xb = x + ((size_t)t * B_ + b) * H_;
    const bool last = (t == T_ - 1);
    const float* xb1 = last ? xb : x + ((size_t)(t + 1) * B_ + b) * H_;
    float* rawn = g_raw[(t + 1) & 1] + b * P_;

    float4 xv[4], x1[4];
#pragma unroll
    for (int j = 0; j < 4; j++) {
        int h = j * 128 + lane * 4;
        xv[j] = *reinterpret_cast<const float4*>(xb + h);
        x1[j] = *reinterpret_cast<const float4*>(xb1 + h);
    }

    float acc[16];
#pragma unroll
    for (int i = 0; i < 16; i++) acc[i] = 0.f;

    int p0 = pblk * RPB + warp * RPW;
    for (int rr = 0; rr < RPW; rr++) {
        int p = p0 + rr;
        float r = rawv[p];
        float logit = (r >= thr) ? r * sc : 0.f;
        float pr = __expf(logit - 10.f) * invden;

        const float* row = src + ((size_t)b * P_ + p) * H_;
        float* wrow = g_pat + ((size_t)b * P_ + p) * H_;

        float4 nv[4];
        float ss = 0.f, d1 = 0.f;
#pragma unroll
        for (int j = 0; j < 4; j++) {
            int h = j * 128 + lane * 4;
            float4 o = *reinterpret_cast<const float4*>(row + h);
            // new_h contribution uses the OLD pat row
            acc[j * 4 + 0] += pr * o.x;
            acc[j * 4 + 1] += pr * o.y;
            acc[j * 4 + 2] += pr * o.z;
            acc[j * 4 + 3] += pr * o.w;
            float4 n;
            n.x = DECAY * o.x + pr * xv[j].x;
            n.y = DECAY * o.y + pr * xv[j].y;
            n.z = DECAY * o.z + pr * xv[j].z;
            n.w = DECAY * o.w + pr * xv[j].w;
            ss += n.x * n.x + n.y * n.y + n.z * n.z + n.w * n.w;
            d1 += n.x * x1[j].x + n.y * x1[j].y + n.z * x1[j].z + n.w * x1[j].w;
            nv[j] = n;
        }
#pragma unroll
        for (int off = 16; off; off >>= 1) {
            ss += __shfl_xor_sync(0xffffffffu, ss, off);
            d1 += __shfl_xor_sync(0xffffffffu, d1, off);
        }
        float inv = 1.f / (sqrtf(ss) + 1e-10f);
#pragma unroll
        for (int j = 0; j < 4; j++) {
            int h = j * 128 + lane * 4;
            float4 w4 = make_float4(nv[j].x * inv, nv[j].y * inv,
                                    nv[j].z * inv, nv[j].w * inv);
            *reinterpret_cast<float4*>(wrow + h) = w4;
        }
        // raw_{t+1} for the normalized row = (pre-norm dot) * inv
        if (lane == 0 && !last) rawn[p] = d1 * inv;
    }

    // ---- reduce new_h partials: regs -> per-warp smem slice -> block -> gmem
    float* sw = s_acc + warp * H_;
#pragma unroll
    for (int j = 0; j < 4; j++) {
        int h = j * 128 + lane * 4;
        *reinterpret_cast<float4*>(sw + h) =
            make_float4(acc[j * 4 + 0], acc[j * 4 + 1], acc[j * 4 + 2], acc[j * 4 + 3]);
    }
    __syncthreads();
    float* op = out + ((size_t)t * B_ + b) * H_;
    for (int h = tid; h < H_; h += 256) {
        float s = 0.f;
#pragma unroll
        for (int w = 0; w < NWARP; w++) s += s_acc[w * H_ + h];
        atomicAdd(op + h, s);
    }
}

// ---------------------------------------------------------------------------
extern "C" void kernel_launch(void* const* d_in, const int* in_sizes, int n_in,
                              void* d_out, int out_size) {
    const float* x = (const float*)d_in[0];
    const float* pat = (const float*)d_in[1];
    // metadata order is x [T,B,H] then pat [B,P,H]; pick by element count to be safe
    if (n_in >= 2 && in_sizes[0] == B_ * P_ * H_) {
        x = (const float*)d_in[1];
        pat = (const float*)d_in[0];
    }
    float* out = (float*)d_out;

    // out is accumulated via atomics — zero it first
    cudaMemsetAsync(d_out, 0, (size_t)out_size * sizeof(float), 0);

    // initial pattern responses from the (already normalized) input pat
    raw0_kernel<<<(B_ * P_) / 8, 256>>>(x, pat);

    // 256 fused recurrence steps
    for (int t = 0; t < T_; t++)
        step_kernel<<<NBLK, 256>>>(x, pat, out, t);
}

// round 5
// speedup vs baseline: 1.0028x; 1.0028x over previous
#include <cuda_runtime.h>
#include <math.h>

// Problem constants
#define T_ 256
#define B_ 64
#define P_ 1024
#define H_ 512

#define DECAY 0.999f

// Step-kernel tiling
#define RPB 64                 // pat rows per block
#define NWARP 8                // warps per block (256 threads)
#define RPW (RPB / NWARP)      // 8 rows per warp
#define BPB (P_ / RPB)         // 16 blocks per batch
#define NBLK (B_ * BPB)        // 1024 blocks per step

// Persistent state (static __device__ scratch — no runtime allocation)
__device__ float g_pat[(size_t)B_ * P_ * H_];   // 128 MB carried pattern state
__device__ float g_raw[2][B_ * P_];             // double-buffered pattern responses

// ---------------------------------------------------------------------------
// raw0: raw[b,p] = pat_in[b,p,:] . x[0,b,:]   (one warp per row)
// ---------------------------------------------------------------------------
__global__ __launch_bounds__(256) void raw0_kernel(const float* __restrict__ x,
                                                   const float* __restrict__ pat) {
    int gw = (blockIdx.x * 256 + threadIdx.x) >> 5;   // global warp = row id
    int lane = threadIdx.x & 31;
    int b = gw >> 10;           // /P_
    int p = gw & (P_ - 1);
    const float* row = pat + ((size_t)b * P_ + p) * H_;
    const float* xb = x + (size_t)b * H_;             // t = 0
    float d = 0.f;
#pragma unroll
    for (int j = 0; j < 4; j++) {
        int h = j * 128 + lane * 4;
        float4 o = *reinterpret_cast<const float4*>(row + h);
        float4 xv = *reinterpret_cast<const float4*>(xb + h);
        d += o.x * xv.x + o.y * xv.y + o.z * xv.z + o.w * xv.w;
    }
#pragma unroll
    for (int off = 16; off; off >>= 1) d += __shfl_xor_sync(0xffffffffu, d, off);
    if (lane == 0) g_raw[0][b * P_ + p] = d;
}

// ---------------------------------------------------------------------------
// One recurrence step, fully fused:
//   - per-block recompute of softmax stats from raw[b,:] (L2-resident, bitwise
//     identical across blocks of the same b)
//   - per row: pr, new_h accumulation (old pat), pat update + L2 normalize,
//     and raw_{t+1} = new_row . x_{t+1} computed from registers
//   - block-reduced new_h partials atomically added into out[t,b,:]
// Block order reverses on odd t so each step's pat read hits the lines the
// previous step wrote last (L2 ping-pong; pat ~ L2 capacity).
// ---------------------------------------------------------------------------
__global__ __launch_bounds__(256) void step_kernel(const float* __restrict__ x,
                                                   const float* __restrict__ pat_in,
                                                   float* __restrict__ out, int t) {
    __shared__ float s_red[256];
    __shared__ float s_acc[NWARP * H_];   // per-warp new_h partials (16 KB)

    int bid = blockIdx.x;
    if (t & 1) bid = NBLK - 1 - bid;      // alternate traversal direction
    int b = bid / BPB;
    int pblk = bid % BPB;
    int tid = threadIdx.x;
    int warp = tid >> 5, lane = tid & 31;

    const float* rawv = g_raw[t & 1] + b * P_;

    // ---- max over raw[b,:] ----
    float lm = -1e30f;
    for (int i = tid; i < P_; i += 256) lm = fmaxf(lm, rawv[i]);
    s_red[tid] = lm;
    __syncthreads();
    for (int s = 128; s > 0; s >>= 1) {
        if (tid < s) s_red[tid] = fmaxf(s_red[tid], s_red[tid + s]);
        __syncthreads();
    }
    float m = s_red[0];
    float thr = 0.9f * m;
    float sc = 10.f / m;
    __syncthreads();

    // ---- softmax denominator: sum exp(logit - 10) ----
    float ls = 0.f;
    for (int i = tid; i < P_; i += 256) {
        float r = rawv[i];
        float logit = (r >= thr) ? r * sc : 0.f;
        ls += __expf(logit - 10.f);
    }
    s_red[tid] = ls;
    __syncthreads();
    for (int s = 128; s > 0; s >>= 1) {
        if (tid < s) s_red[tid] += s_red[tid + s];
        __syncthreads();
    }
    float invden = 1.f / s_red[0];

    // ---- main per-row work ----
    const float* src = (t == 0) ? pat_in : (const float*)g_pat;
    const float* xb = x + ((size_t)t * B_ + b) * H_;
    const bool last = (t == T_ - 1);
    const float* xb1 = last ? xb : x + ((size_t)(t + 1) * B_ + b) * H_;
    float* rawn = g_raw[(t + 1) & 1] + b * P_;

    float4 xv[4], x1[4];
#pragma unroll
    for (int j = 0; j < 4; j++) {
        int h = j * 128 + lane * 4;
        xv[j] = *reinterpret_cast<const float4*>(xb + h);
        x1[j] = *reinterpret_cast<const float4*>(xb1 + h);
    }

    float acc[16];
#pragma unroll
    for (int i = 0; i < 16; i++) acc[i] = 0.f;

    int p0 = pblk * RPB + warp * RPW;
    for (int rr = 0; rr < RPW; rr++) {
        int p = p0 + rr;
        float r = rawv[p];
        float logit = (r >= thr) ? r * sc : 0.f;
        float pr = __expf(logit - 10.f) * invden;

        const float* row = src + ((size_t)b * P_ + p) * H_;
        float* wrow = g_pat + ((size_t)b * P_ + p) * H_;

        float4 nv[4];
        float ss = 0.f, d1 = 0.f;
#pragma unroll
        for (int j = 0; j < 4; j++) {
            int h = j * 128 + lane * 4;
            float4 o = *reinterpret_cast<const float4*>(row + h);
            // new_h contribution uses the OLD pat row
            acc[j * 4 + 0] += pr * o.x;
            acc[j * 4 + 1] += pr * o.y;
            acc[j * 4 + 2] += pr * o.z;
            acc[j * 4 + 3] += pr * o.w;
            float4 n;
            n.x = DECAY * o.x + pr * xv[j].x;
            n.y = DECAY * o.y + pr * xv[j].y;
            n.z = DECAY * o.z + pr * xv[j].z;
            n.w = DECAY * o.w + pr * xv[j].w;
            ss += n.x * n.x + n.y * n.y + n.z * n.z + n.w * n.w;
            d1 += n.x * x1[j].x + n.y * x1[j].y + n.z * x1[j].z + n.w * x1[j].w;
            nv[j] = n;
        }
#pragma unroll
        for (int off = 16; off; off >>= 1) {
            ss += __shfl_xor_sync(0xffffffffu, ss, off);
            d1 += __shfl_xor_sync(0xffffffffu, d1, off);
        }
        float inv = 1.f / (sqrtf(ss) + 1e-10f);
#pragma unroll
        for (int j = 0; j < 4; j++) {
            int h = j * 128 + lane * 4;
            float4 w4 = make_float4(nv[j].x * inv, nv[j].y * inv,
                                    nv[j].z * inv, nv[j].w * inv);
            *reinterpret_cast<float4*>(wrow + h) = w4;
        }
        // raw_{t+1} for the normalized row = (pre-norm dot) * inv
        if (lane == 0 && !last) rawn[p] = d1 * inv;
    }

    // ---- reduce new_h partials: regs -> per-warp smem slice -> block -> gmem
    float* sw = s_acc + warp * H_;
#pragma unroll
    for (int j = 0; j < 4; j++) {
        int h = j * 128 + lane * 4;
        *reinterpret_cast<float4*>(sw + h) =
            make_float4(acc[j * 4 + 0], acc[j * 4 + 1], acc[j * 4 + 2], acc[j * 4 + 3]);
    }
    __syncthreads();
    float* op = out + ((size_t)t * B_ + b) * H_;
    for (int h = tid; h < H_; h += 256) {
        float s = 0.f;
#pragma unroll
        for (int w = 0; w < NWARP; w++) s += s_acc[w * H_ + h];
        atomicAdd(op + h, s);
    }
}

// ---------------------------------------------------------------------------
extern "C" void kernel_launch(void* const* d_in, const int* in_sizes, int n_in,
                              void* d_out, int out_size) {
    const float* x = (const float*)d_in[0];
    const float* pat = (const float*)d_in[1];
    // metadata order is x [T,B,H] then pat [B,P,H]; pick by element count to be safe
    if (n_in >= 2 && in_sizes[0] == B_ * P_ * H_) {
        x = (const float*)d_in[1];
        pat = (const float*)d_in[0];
    }
    float* out = (float*)d_out;

    // out is accumulated via atomics — zero it first
    cudaMemsetAsync(d_out, 0, (size_t)out_size * sizeof(float), 0);

    // initial pattern responses from the (already normalized) input pat
    raw0_kernel<<<(B_ * P_) / 8, 256>>>(x, pat);

    // 256 fused recurrence steps
    for (int t = 0; t < T_; t++)
        step_kernel<<<NBLK, 256>>>(x, pat, out, t);
}

// round 8
// speedup vs baseline: 1.3730x; 1.3691x over previous
#include <cuda_runtime.h>
#include <math.h>

#define T_ 256
#define B_ 64
#define P_ 1024
#define H_ 512
#define C_ 16
#define NCH_ (T_ / C_)
#define DECAY 0.999f
#define DECAY_D 0.999
#define D2_D 0.998001

// Persistent scratch (static __device__ — no runtime allocation)
__device__ float g_pat[(size_t)B_ * P_ * H_];       // 128 MB carried state
__device__ float g_Q[2][(size_t)B_ * P_ * C_];      // Q[b][p][tau]
__device__ float g_W [(size_t)B_ * C_ * P_];        // W[b][tl][p] = pr*alpha_pre
__device__ float g_Bc[(size_t)B_ * C_ * P_];        // Bc[b][s][p] = f_s at chunk end
__device__ float g_A [B_ * P_];                     // alpha at chunk end
__device__ float g_G [B_ * NCH_ * C_ * C_];         // within-chunk Gram (fp64-accumulated)
__device__ float g_Xn[T_ * B_];                     // ||x_t||^2
__device__ float g_Gam[B_ * C_ * C_];               // gamma[b][tl][s]

// ---------------------------------------------------------------------------
// Gram + norms per (b, chunk): G[s][t] = x_{t0+s}.x_{t0+t} (s<=t), fp64 accum.
// ---------------------------------------------------------------------------
__global__ __launch_bounds__(256) void xstats_kernel(const float* __restrict__ x) {
    __shared__ float sx[C_ * H_];
    int b = blockIdx.x >> 4;
    int c = blockIdx.x & 15;
    int t0 = c * C_;
    {
        int tau = threadIdx.x >> 4, l16 = threadIdx.x & 15;
        const float4* xs = (const float4*)(x + ((size_t)(t0 + tau) * B_ + b) * H_);
        float4* d = (float4*)(sx + tau * H_);
#pragma unroll
        for (int k = 0; k < 8; k++) d[l16 + 16 * k] = xs[l16 + 16 * k];
    }
    __syncthreads();
    int w = threadIdx.x >> 5, lane = threadIdx.x & 31;
    for (int id = w; id < C_ * C_; id += 8) {
        int s = id >> 4, t = id & 15;
        if (s > t) continue;
        double acc = 0.0;
#pragma unroll
        for (int k = 0; k < 16; k++) {
            int h = lane + 32 * k;
            acc += (double)sx[s * H_ + h] * (double)sx[t * H_ + h];
        }
#pragma unroll
        for (int o = 16; o; o >>= 1) acc += __shfl_xor_sync(~0u, acc, o);
        if (lane == 0) {
            g_G[(((size_t)b * NCH_ + c) * C_ + s) * C_ + t] = (float)acc;
            if (s == t) g_Xn[(t0 + t) * B_ + b] = (float)acc;
        }
    }
}

// ---------------------------------------------------------------------------
// Q[buf][b][p][tau] = src_row(b,p) . x[t0+tau]   (fp32, pairwise shfl tree)
// ---------------------------------------------------------------------------
__global__ __launch_bounds__(256) void qk_kernel(const float* __restrict__ x,
                                                 const float* __restrict__ pat_in,
                                                 int t0, int buf, int useInit) {
    __shared__ float sx[C_ * H_];
    const float* src = useInit ? pat_in : (const float*)g_pat;
    int b = blockIdx.x >> 6;
    int p0 = (blockIdx.x & 63) * 16;
    {
        int tau = threadIdx.x >> 4, l16 = threadIdx.x & 15;
        const float4* xs = (const float4*)(x + ((size_t)(t0 + tau) * B_ + b) * H_);
        float4* d = (float4*)(sx + tau * H_);
#pragma unroll
        for (int k = 0; k < 8; k++) d[l16 + 16 * k] = xs[l16 + 16 * k];
    }
    __syncthreads();
    int w = threadIdx.x >> 5, lane = threadIdx.x & 31;
    int p = p0 + w * 2;
    const float4* r0 = (const float4*)(src + ((size_t)b * P_ + p) * H_);
    const float4* r1 = (const float4*)(src + ((size_t)b * P_ + p + 1) * H_);
    float4 a0[4], a1[4];
#pragma unroll
    for (int j = 0; j < 4; j++) { a0[j] = r0[j * 32 + lane]; a1[j] = r1[j * 32 + lane]; }
    float q0[C_], q1[C_];
#pragma unroll
    for (int t = 0; t < C_; t++) { q0[t] = 0.f; q1[t] = 0.f; }
#pragma unroll
    for (int j = 0; j < 4; j++) {
#pragma unroll
        for (int t = 0; t < C_; t++) {
            float4 xv = *(const float4*)(sx + t * H_ + j * 128 + lane * 4);
            q0[t] += a0[j].x * xv.x + a0[j].y * xv.y + a0[j].z * xv.z + a0[j].w * xv.w;
            q1[t] += a1[j].x * xv.x + a1[j].y * xv.y + a1[j].z * xv.z + a1[j].w * xv.w;
        }
    }
#pragma unroll
    for (int t = 0; t < C_; t++) {
#pragma unroll
        for (int o = 16; o; o >>= 1) {
            q0[t] += __shfl_xor_sync(~0u, q0[t], o);
            q1[t] += __shfl_xor_sync(~0u, q1[t], o);
        }
    }
    float s0 = q0[0], s1 = q1[0];
#pragma unroll
    for (int t = 1; t < C_; t++) {
        s0 = (lane == t) ? q0[t] : s0;
        s1 = (lane == t) ? q1[t] : s1;
    }
    if (lane < C_) {
        g_Q[buf][((size_t)b * P_ + p) * C_ + lane] = s0;
        g_Q[buf][((size_t)b * P_ + p + 1) * C_ + lane] = s1;
    }
}

// ---------------------------------------------------------------------------
// Coefficient-space scan, trajectory state in FP64:
//   raw_tl = alpha*q[tl] + sum_{s<tl} f_s*G[s,tl]       (fp64 accum)
//   nu     = sqrt(D^2 + 2 D pr raw + pr^2 ||x||^2)+1e-10 (fp64)
//   f_s *= D/nu; f_tl = pr/nu; alpha *= D/nu             (fp64 chain)
// Mask/softmax comparisons in fp32 (reference semantics). One block per batch.
// ---------------------------------------------------------------------------
__global__ __launch_bounds__(1024, 1) void scan_kernel(int c) {
    __shared__ float sG[C_][C_];
    __shared__ float sXn[C_];
    __shared__ float s_red[32];
    __shared__ float sval;
    __shared__ float sgp[120][33];
    int b = blockIdx.x;
    int p = threadIdx.x;
    int lane = p & 31, wid = p >> 5;
    if (p < 256) sG[p >> 4][p & 15] =
        g_G[(((size_t)b * NCH_ + c) * C_ + (p >> 4)) * C_ + (p & 15)];
    if (p < C_) sXn[p] = g_Xn[(c * C_ + p) * B_ + b];
    __syncthreads();

    float q[C_];
    {
        const float4* q4 = (const float4*)(g_Q[c & 1] + ((size_t)b * P_ + p) * C_);
#pragma unroll
        for (int k = 0; k < 4; k++) {
            float4 v = q4[k];
            q[4 * k] = v.x; q[4 * k + 1] = v.y; q[4 * k + 2] = v.z; q[4 * k + 3] = v.w;
        }
    }
    double f[C_];
    double alpha = 1.0;
#pragma unroll
    for (int tl = 0; tl < C_; tl++) {
        double rawd = alpha * (double)q[tl];
#pragma unroll
        for (int s = 0; s < C_; s++) if (s < tl) rawd += f[s] * (double)sG[s][tl];
        float raw = (float)rawd;

        // block max (fp32, matching reference compare precision)
        float m = raw;
#pragma unroll
        for (int o = 16; o; o >>= 1) m = fmaxf(m, __shfl_xor_sync(~0u, m, o));
        if (lane == 0) s_red[wid] = m;
        __syncthreads();
        if (wid == 0) {
            float v = s_red[lane];
#pragma unroll
            for (int o = 16; o; o >>= 1) v = fmaxf(v, __shfl_xor_sync(~0u, v, o));
            if (lane == 0) sval = v;
        }
        __syncthreads();
        m = sval;
        float thr = 0.9f * m, sc = 10.f / m;
        float logit = (raw >= thr) ? raw * sc : 0.f;
        float ex = __expf(logit - 10.f);
        float sum = ex;
#pragma unroll
        for (int o = 16; o; o >>= 1) sum += __shfl_xor_sync(~0u, sum, o);
        if (lane == 0) s_red[wid] = sum;
        __syncthreads();
        if (wid == 0) {
            float v = s_red[lane];
#pragma unroll
            for (int o = 16; o; o >>= 1) v += __shfl_xor_sync(~0u, v, o);
            if (lane == 0) sval = v;
        }
        __syncthreads();
        float pr = ex / sval;

        // gamma partials with PRE-update f: gamma[tl][s] = sum_p pr*f_s
#pragma unroll
        for (int s = 0; s < C_; s++) if (s < tl) {
            float v = pr * (float)f[s];
#pragma unroll
            for (int o = 16; o; o >>= 1) v += __shfl_xor_sync(~0u, v, o);
            if (lane == 0) sgp[tl * (tl - 1) / 2 + s][wid] = v;
        }

        g_W[((size_t)b * C_ + tl) * P_ + p] = (float)((double)pr * alpha);

        double prd = (double)pr;
        double nu = sqrt(fma(prd * prd, (double)sXn[tl],
                             fma(2.0 * DECAY_D * prd, rawd, D2_D))) + 1e-10;
        double r = DECAY_D / nu;
#pragma unroll
        for (int s = 0; s < C_; s++) if (s < tl) f[s] *= r;
        f[tl] = prd / nu;
        alpha *= r;
        __syncthreads();
    }
#pragma unroll
    for (int s = 0; s < C_; s++)
        g_Bc[((size_t)b * C_ + s) * P_ + p] = (float)f[s];
    g_A[b * P_ + p] = (float)alpha;

    __syncthreads();
    if (p < 256) {
        int tl = p >> 4, s = p & 15;
        float g = 0.f;
        if (s < tl) {
            int id = tl * (tl - 1) / 2 + s;
            for (int k = 0; k < 32; k++) g += sgp[id][k];
        }
        g_Gam[(b * C_ + tl) * C_ + s] = g;
    }
}

// ---------------------------------------------------------------------------
// Apply: new_pat = A*P0 + sum_s Bc[s]*x_s; out[t0+tl] += sum_p W[tl,p]*P0[p,:]
// (+ gamma*x for ptile 0). Thread owns float2 of H; block covers 128 rows.
// ---------------------------------------------------------------------------
__global__ __launch_bounds__(256) void apply_kernel(const float* __restrict__ x,
                                                    const float* __restrict__ pat_in,
                                                    float* __restrict__ out, int c) {
    __shared__ float sA[128];
    __shared__ float sB[C_][128];
    __shared__ float sW[C_][128];
    __shared__ float sGm[C_ * C_];
    const float* src = (c == 0) ? pat_in : (const float*)g_pat;
    int b = blockIdx.x >> 3;
    int pt = blockIdx.x & 7;
    int p0 = pt * 128;
    int tid = threadIdx.x;
    int t0 = c * C_;

    if (tid < 128) sA[tid] = g_A[b * P_ + p0 + tid];
#pragma unroll
    for (int k = 0; k < 8; k++) {
        int i = tid + 256 * k;
        int tl = i >> 7, r = i & 127;
        sB[tl][r] = g_Bc[((size_t)b * C_ + tl) * P_ + p0 + r];
        sW[tl][r] = g_W [((size_t)b * C_ + tl) * P_ + p0 + r];
    }
    if (pt == 0) sGm[tid] = g_Gam[b * 256 + tid];
    __syncthreads();

    int h = tid * 2;
    float2 xr[C_];
#pragma unroll
    for (int s = 0; s < C_; s++)
        xr[s] = *(const float2*)(x + ((size_t)(t0 + s) * B_ + b) * H_ + h);
    float2 acc[C_];
#pragma unroll
    for (int tl = 0; tl < C_; tl++) { acc[tl].x = 0.f; acc[tl].y = 0.f; }

    const float* srow = src + ((size_t)b * P_ + p0) * H_ + h;
    float* drow = g_pat + ((size_t)b * P_ + p0) * H_ + h;
    for (int r = 0; r < 128; r++) {
        float2 pv = *(const float2*)srow; srow += H_;
        float a = sA[r];
        float2 nv; nv.x = a * pv.x; nv.y = a * pv.y;
#pragma unroll
        for (int s = 0; s < C_; s++) {
            float bs = sB[s][r];
            nv.x += bs * xr[s].x; nv.y += bs * xr[s].y;
        }
        *(float2*)drow = nv; drow += H_;
#pragma unroll
        for (int tl = 0; tl < C_; tl++) {
            float wv = sW[tl][r];
            acc[tl].x += wv * pv.x; acc[tl].y += wv * pv.y;
        }
    }
    if (pt == 0) {
#pragma unroll
        for (int tl = 0; tl < C_; tl++)
#pragma unroll
            for (int s = 0; s < C_; s++) {
                float g = sGm[tl * C_ + s];
                acc[tl].x += g * xr[s].x; acc[tl].y += g * xr[s].y;
            }
    }
#pragma unroll
    for (int tl = 0; tl < C_; tl++) {
        float* op = out + ((size_t)(t0 + tl) * B_ + b) * H_ + h;
        atomicAdd(op, acc[tl].x);
        atomicAdd(op + 1, acc[tl].y);
    }
}

// ---------------------------------------------------------------------------
extern "C" void kernel_launch(void* const* d_in, const int* in_sizes, int n_in,
                              void* d_out, int out_size) {
    const float* x = (const float*)d_in[0];
    const float* pat = (const float*)d_in[1];
    if (n_in >= 2 && in_sizes[0] == B_ * P_ * H_) {
        x = (const float*)d_in[1];
        pat = (const float*)d_in[0];
    }
    float* out = (float*)d_out;

    cudaMemsetAsync(d_out, 0, (size_t)out_size * sizeof(float), 0);
    xstats_kernel<<<B_ * NCH_, 256>>>(x);
    qk_kernel<<<B_ * 64, 256>>>(x, pat, 0, 0, 1);

    for (int c = 0; c < NCH_; c++) {
        scan_kernel<<<B_, 1024>>>(c);
        apply_kernel<<<B_ * 8, 256>>>(x, pat, out, c);
        if (c + 1 < NCH_)
            qk_kernel<<<B_ * 64, 256>>>(x, pat, (c + 1) * C_, (c + 1) & 1, 0);
    }
}

// round 9
// speedup vs baseline: 2.6163x; 1.9056x over previous
#include <cuda_runtime.h>
#include <math.h>

#define T_ 256
#define B_ 64
#define P_ 1024
#define H_ 512
#define C_ 16
#define NCH_ (T_ / C_)
#define DECAY 0.999f

// Persistent scratch (static __device__ — no runtime allocation)
__device__ float g_pat[(size_t)B_ * P_ * H_];       // 128 MB carried state
__device__ float g_Q[2][(size_t)B_ * P_ * C_];      // Q[b][p][tau]
__device__ float g_W [(size_t)B_ * C_ * P_];        // W[b][tl][p] = pr*alpha_pre
__device__ float g_Bc[(size_t)B_ * C_ * P_];        // Bc[b][s][p] = f_s at chunk end
__device__ float g_A [B_ * P_];                     // alpha at chunk end
__device__ float g_G [B_ * NCH_ * C_ * C_];         // within-chunk Gram (fp64-accumulated)
__device__ float g_Xn[T_ * B_];                     // ||x_t||^2
__device__ float g_Gam[B_ * C_ * C_];               // gamma[b][tl][s]

// ===========================================================================
// Double-float (compensated fp32) helpers. All rounding-sensitive adds use
// __fadd_rn/__fsub_rn intrinsics so no compiler reassociation can break them.
// ===========================================================================
struct DF { float h, l; };

__device__ __forceinline__ DF df_renorm(float h, float l) {   // |h| >= |l|
    float s = __fadd_rn(h, l);
    float e = __fsub_rn(l, __fsub_rn(s, h));
    DF r; r.h = s; r.l = e; return r;
}
__device__ __forceinline__ DF df_two_sum(float a, float b) {
    float s = __fadd_rn(a, b);
    float bb = __fsub_rn(s, a);
    float e = __fadd_rn(__fsub_rn(a, __fsub_rn(s, bb)), __fsub_rn(b, bb));
    DF r; r.h = s; r.l = e; return r;
}
__device__ __forceinline__ DF df_mul(DF a, DF b) {
    float p = __fmul_rn(a.h, b.h);
    float e = fmaf(a.h, b.h, -p);
    e = fmaf(a.h, b.l, e);
    e = fmaf(a.l, b.h, e);
    return df_renorm(p, e);
}
__device__ __forceinline__ DF df_mul_f(DF a, float b) {
    float p = __fmul_rn(a.h, b);
    float e = fmaf(a.h, b, -p);
    e = fmaf(a.l, b, e);
    return df_renorm(p, e);
}
__device__ __forceinline__ DF df_add(DF a, DF b) {
    DF s = df_two_sum(a.h, b.h);
    float e = __fadd_rn(s.l, __fadd_rn(a.l, b.l));
    return df_renorm(s.h, e);
}
__device__ __forceinline__ DF df_add_f(DF a, float b) {
    DF s = df_two_sum(a.h, b);
    float e = __fadd_rn(s.l, a.l);
    return df_renorm(s.h, e);
}

// DF constants for D=0.999, D^2, 2D (hi = fp32 round, lo = residual)
#define D_HI   ((float)0.999)
#define D_LO   ((float)(0.999 - (double)((float)0.999)))
#define D2_HI  ((float)0.998001)
#define D2_LO  ((float)(0.998001 - (double)((float)0.998001)))
#define TD_HI  ((float)1.998)
#define TD_LO  ((float)(1.998 - (double)((float)1.998)))

// ---------------------------------------------------------------------------
// Gram + norms per (b, chunk): G[s][t] = x_{t0+s}.x_{t0+t} (s<=t), fp64 accum
// (tiny volume; keeps Gram at ~1e-16).
// ---------------------------------------------------------------------------
__global__ __launch_bounds__(256) void xstats_kernel(const float* __restrict__ x) {
    __shared__ float sx[C_ * H_];
    int b = blockIdx.x >> 4;
    int c = blockIdx.x & 15;
    int t0 = c * C_;
    {
        int tau = threadIdx.x >> 4, l16 = threadIdx.x & 15;
        const float4* xs = (const float4*)(x + ((size_t)(t0 + tau) * B_ + b) * H_);
        float4* d = (float4*)(sx + tau * H_);
#pragma unroll
        for (int k = 0; k < 8; k++) d[l16 + 16 * k] = xs[l16 + 16 * k];
    }
    __syncthreads();
    int w = threadIdx.x >> 5, lane = threadIdx.x & 31;
    for (int id = w; id < C_ * C_; id += 8) {
        int s = id >> 4, t = id & 15;
        if (s > t) continue;
        double acc = 0.0;
#pragma unroll
        for (int k = 0; k < 16; k++) {
            int h = lane + 32 * k;
            acc += (double)sx[s * H_ + h] * (double)sx[t * H_ + h];
        }
#pragma unroll
        for (int o = 16; o; o >>= 1) acc += __shfl_xor_sync(~0u, acc, o);
        if (lane == 0) {
            g_G[(((size_t)b * NCH_ + c) * C_ + s) * C_ + t] = (float)acc;
            if (s == t) g_Xn[(t0 + t) * B_ + b] = (float)acc;
        }
    }
}

// ---------------------------------------------------------------------------
// Q[buf][b][p][tau] = src_row(b,p) . x[t0+tau]   (fp32, pairwise shfl tree)
// ---------------------------------------------------------------------------
__global__ __launch_bounds__(256) void qk_kernel(const float* __restrict__ x,
                                                 const float* __restrict__ pat_in,
                                                 int t0, int buf, int useInit) {
    __shared__ float sx[C_ * H_];
    const float* src = useInit ? pat_in : (const float*)g_pat;
    int b = blockIdx.x >> 6;
    int p0 = (blockIdx.x & 63) * 16;
    {
        int tau = threadIdx.x >> 4, l16 = threadIdx.x & 15;
        const float4* xs = (const float4*)(x + ((size_t)(t0 + tau) * B_ + b) * H_);
        float4* d = (float4*)(sx + tau * H_);
#pragma unroll
        for (int k = 0; k < 8; k++) d[l16 + 16 * k] = xs[l16 + 16 * k];
    }
    __syncthreads();
    int w = threadIdx.x >> 5, lane = threadIdx.x & 31;
    int p = p0 + w * 2;
    const float4* r0 = (const float4*)(src + ((size_t)b * P_ + p) * H_);
    const float4* r1 = (const float4*)(src + ((size_t)b * P_ + p + 1) * H_);
    float4 a0[4], a1[4];
#pragma unroll
    for (int j = 0; j < 4; j++) { a0[j] = r0[j * 32 + lane]; a1[j] = r1[j * 32 + lane]; }
    float q0[C_], q1[C_];
#pragma unroll
    for (int t = 0; t < C_; t++) { q0[t] = 0.f; q1[t] = 0.f; }
#pragma unroll
    for (int j = 0; j < 4; j++) {
#pragma unroll
        for (int t = 0; t < C_; t++) {
            float4 xv = *(const float4*)(sx + t * H_ + j * 128 + lane * 4);
            q0[t] += a0[j].x * xv.x + a0[j].y * xv.y + a0[j].z * xv.z + a0[j].w * xv.w;
            q1[t] += a1[j].x * xv.x + a1[j].y * xv.y + a1[j].z * xv.z + a1[j].w * xv.w;
        }
    }
#pragma unroll
    for (int t = 0; t < C_; t++) {
#pragma unroll
        for (int o = 16; o; o >>= 1) {
            q0[t] += __shfl_xor_sync(~0u, q0[t], o);
            q1[t] += __shfl_xor_sync(~0u, q1[t], o);
        }
    }
    float s0 = q0[0], s1 = q1[0];
#pragma unroll
    for (int t = 1; t < C_; t++) {
        s0 = (lane == t) ? q0[t] : s0;
        s1 = (lane == t) ? q1[t] : s1;
    }
    if (lane < C_) {
        g_Q[buf][((size_t)b * P_ + p) * C_ + lane] = s0;
        g_Q[buf][((size_t)b * P_ + p + 1) * C_ + lane] = s1;
    }
}

// ---------------------------------------------------------------------------
// Coefficient-space scan, trajectory state in DOUBLE-FLOAT (fp64-class
// precision at fp32-pipe speed):
//   raw_tl = alpha*q[tl] + sum_{s<tl} f_s*G[s,tl]   (DF accumulation)
//   nu^2   = D^2 + 2 D pr raw + pr^2 ||x||^2        (DF)
//   1/nu   = rsqrtf + one DF Newton                 (~1e-13)
//   f_s *= D/nu; f_tl = pr/nu; alpha *= D/nu        (DF chain)
// Mask/softmax comparisons in fp32 (reference semantics). q lives in dynamic
// smem (per-thread private slots) to keep f_hi/f_lo register-resident.
// ---------------------------------------------------------------------------
extern __shared__ float s_dyn[];   // q: [C_][1024]

__global__ __launch_bounds__(1024, 1) void scan_kernel(int c) {
    __shared__ float sG[C_][C_];
    __shared__ float sXn[C_];
    __shared__ float s_red[32];
    __shared__ float sval;
    __shared__ float sgp[120][33];
    float* s_q = s_dyn;

    int b = blockIdx.x;
    int p = threadIdx.x;
    int lane = p & 31, wid = p >> 5;
    if (p < 256) sG[p >> 4][p & 15] =
        g_G[(((size_t)b * NCH_ + c) * C_ + (p >> 4)) * C_ + (p & 15)];
    if (p < C_) sXn[p] = g_Xn[(c * C_ + p) * B_ + b];

    {   // stage q into private smem slots (no cross-thread use -> no sync needed)
        const float4* q4 = (const float4*)(g_Q[c & 1] + ((size_t)b * P_ + p) * C_);
#pragma unroll
        for (int k = 0; k < 4; k++) {
            float4 v = q4[k];
            s_q[(4 * k + 0) * 1024 + p] = v.x;
            s_q[(4 * k + 1) * 1024 + p] = v.y;
            s_q[(4 * k + 2) * 1024 + p] = v.z;
            s_q[(4 * k + 3) * 1024 + p] = v.w;
        }
    }
    __syncthreads();

    float fh[C_], fl[C_];
    DF alpha; alpha.h = 1.f; alpha.l = 0.f;
    const DF D_DF  = {D_HI,  D_LO};
    const DF D2_DF = {D2_HI, D2_LO};
    const DF TD_DF = {TD_HI, TD_LO};

#pragma unroll
    for (int tl = 0; tl < C_; tl++) {
        // ---- raw (DF accumulation) ----
        DF acc = df_mul_f(alpha, s_q[tl * 1024 + p]);
#pragma unroll
        for (int s = 0; s < C_; s++) if (s < tl) {
            float g = sG[s][tl];
            float pp = __fmul_rn(fh[s], g);
            float ee = fmaf(fh[s], g, -pp);
            ee = fmaf(fl[s], g, ee);
            DF term; term.h = pp; term.l = ee;
            acc = df_add(acc, term);
        }
        float raw = __fadd_rn(acc.h, acc.l);

        // ---- block max (fp32, reference compare precision) ----
        float m = raw;
#pragma unroll
        for (int o = 16; o; o >>= 1) m = fmaxf(m, __shfl_xor_sync(~0u, m, o));
        if (lane == 0) s_red[wid] = m;
        __syncthreads();
        if (wid == 0) {
            float v = s_red[lane];
#pragma unroll
            for (int o = 16; o; o >>= 1) v = fmaxf(v, __shfl_xor_sync(~0u, v, o));
            if (lane == 0) sval = v;
        }
        __syncthreads();
        m = sval;
        float thr = 0.9f * m, sc = 10.f / m;
        float logit = (raw >= thr) ? raw * sc : 0.f;
        float ex = __expf(logit - 10.f);
        float sum = ex;
#pragma unroll
        for (int o = 16; o; o >>= 1) sum += __shfl_xor_sync(~0u, sum, o);
        if (lane == 0) s_red[wid] = sum;
        __syncthreads();
        if (wid == 0) {
            float v = s_red[lane];
#pragma unroll
            for (int o = 16; o; o >>= 1) v += __shfl_xor_sync(~0u, v, o);
            if (lane == 0) sval = v;
        }
        __syncthreads();
        float pr = ex / sval;

        // ---- gamma partials with PRE-update f ----
#pragma unroll
        for (int s = 0; s < C_; s++) if (s < tl) {
            float v = pr * fh[s];
#pragma unroll
            for (int o = 16; o; o >>= 1) v += __shfl_xor_sync(~0u, v, o);
            if (lane == 0) sgp[tl * (tl - 1) / 2 + s][wid] = v;
        }

        // W with pre-update alpha
        g_W[((size_t)b * C_ + tl) * P_ + p] = fmaf(pr, alpha.l, __fmul_rn(pr, alpha.h));

        // ---- nu^2 = D2 + 2D*pr*raw + pr^2*Xn (DF) ----
        DF c2dpr = df_mul_f(TD_DF, pr);
        DF t1 = df_mul(c2dpr, acc);
        float ph = __fmul_rn(pr, pr);
        float pe = fmaf(pr, pr, -ph);
        DF prsq; prsq.h = ph; prsq.l = pe;
        DF t2 = df_mul_f(prsq, sXn[tl]);
        DF arg = df_add(df_add(D2_DF, t1), t2);

        // ---- 1/nu via rsqrtf + one DF Newton ----
        float y0 = rsqrtf(arg.h);
        float qh = __fmul_rn(y0, y0);
        float qe = fmaf(y0, y0, -qh);
        DF y0sq; y0sq.h = qh; y0sq.l = qe;
        DF t = df_mul(arg, y0sq);
        DF negt; negt.h = -t.h; negt.l = -t.l;
        DF hdf = df_add_f(negt, 1.0f);
        float corr = 0.5f * y0 * __fadd_rn(hdf.h, hdf.l);
        DF inu = df_two_sum(y0, corr);

        // ---- chain updates ----
        DF r_ = df_mul(D_DF, inu);
#pragma unroll
        for (int s = 0; s < C_; s++) if (s < tl) {
            DF fs; fs.h = fh[s]; fs.l = fl[s];
            fs = df_mul(fs, r_);
            fh[s] = fs.h; fl[s] = fs.l;
        }
        DF ftl = df_mul_f(inu, pr);
        fh[tl] = ftl.h; fl[tl] = ftl.l;
        alpha = df_mul(alpha, r_);
    }

#pragma unroll
    for (int s = 0; s < C_; s++)
        g_Bc[((size_t)b * C_ + s) * P_ + p] = __fadd_rn(fh[s], fl[s]);
    g_A[b * P_ + p] = __fadd_rn(alpha.h, alpha.l);

    __syncthreads();
    if (p < 256) {
        int tl = p >> 4, s = p & 15;
        float g = 0.f;
        if (s < tl) {
            int id = tl * (tl - 1) / 2 + s;
            for (int k = 0; k < 32; k++) g += sgp[id][k];
        }
        g_Gam[(b * C_ + tl) * C_ + s] = g;
    }
}

// ---------------------------------------------------------------------------
// Apply: new_pat = A*P0 + sum_s Bc[s]*x_s; out[t0+tl] += sum_p W[tl,p]*P0[p,:]
// (+ gamma*x for ptile 0). Coefficients repacked r-major so each r-iteration
// reads 8x LDS.128 + 1 scalar instead of 33 scalar LDS.
// ---------------------------------------------------------------------------
__global__ __launch_bounds__(256) void apply_kernel(const float* __restrict__ x,
                                                    const float* __restrict__ pat_in,
                                                    float* __restrict__ out, int c) {
    __shared__ float sC[128][36];   // [r][0..15]=B, [16..31]=W, [32]=A (rows 16B-aligned)
    __shared__ float sGm[C_ * C_];
    const float* src = (c == 0) ? pat_in : (const float*)g_pat;
    int b = blockIdx.x >> 3;
    int pt = blockIdx.x & 7;
    int p0 = pt * 128;
    int tid = threadIdx.x;
    int t0 = c * C_;

#pragma unroll
    for (int k = 0; k < 8; k++) {
        int i = tid + 256 * k;        // i < 2048
        int tl = i >> 7, r = i & 127;
        sC[r][tl]      = g_Bc[((size_t)b * C_ + tl) * P_ + p0 + r];
        sC[r][16 + tl] = g_W [((size_t)b * C_ + tl) * P_ + p0 + r];
    }
    if (tid < 128) sC[tid][32] = g_A[b * P_ + p0 + tid];
    if (pt == 0) sGm[tid] = g_Gam[b * 256 + tid];
    __syncthreads();

    int h = tid * 2;
    float2 xr[C_];
#pragma unroll
    for (int s = 0; s < C_; s++)
        xr[s] = *(const float2*)(x + ((size_t)(t0 + s) * B_ + b) * H_ + h);
    float2 acc[C_];
#pragma unroll
    for (int tl = 0; tl < C_; tl++) { acc[tl].x = 0.f; acc[tl].y = 0.f; }

    const float* srow = src + ((size_t)b * P_ + p0) * H_ + h;
    float* drow = g_pat + ((size_t)b * P_ + p0) * H_ + h;
    for (int r = 0; r < 128; r++) {
        float2 pv = *(const float2*)srow; srow += H_;
        const float4* crow = (const float4*)&sC[r][0];
        float cb[16], cw[16];
        *(float4*)&cb[0]  = crow[0]; *(float4*)&cb[4]  = crow[1];
        *(float4*)&cb[8]  = crow[2]; *(float4*)&cb[12] = crow[3];
        *(float4*)&cw[0]  = crow[4]; *(float4*)&cw[4]  = crow[5];
        *(float4*)&cw[8]  = crow[6]; *(float4*)&cw[12] = crow[7];
        float a = sC[r][32];
        float2 nv; nv.x = a * pv.x; nv.y = a * pv.y;
#pragma unroll
        for (int s = 0; s < C_; s++) {
            nv.x += cb[s] * xr[s].x; nv.y += cb[s] * xr[s].y;
        }
        *(float2*)drow = nv; drow += H_;
#pragma unroll
        for (int tl = 0; tl < C_; tl++) {
            acc[tl].x += cw[tl] * pv.x; acc[tl].y += cw[tl] * pv.y;
        }
    }
    if (pt == 0) {
#pragma unroll
        for (int tl = 0; tl < C_; tl++)
#pragma unroll
            for (int s = 0; s < C_; s++) {
                float g = sGm[tl * C_ + s];
                acc[tl].x += g * xr[s].x; acc[tl].y += g * xr[s].y;
            }
    }
#pragma unroll
    for (int tl = 0; tl < C_; tl++) {
        float* op = out + ((size_t)(t0 + tl) * B_ + b) * H_ + h;
        atomicAdd(op, acc[tl].x);
        atomicAdd(op + 1, acc[tl].y);
    }
}

// ---------------------------------------------------------------------------
extern "C" void kernel_launch(void* const* d_in, const int* in_sizes, int n_in,
                              void* d_out, int out_size) {
    const float* x = (const float*)d_in[0];
    const float* pat = (const float*)d_in[1];
    if (n_in >= 2 && in_sizes[0] == B_ * P_ * H_) {
        x = (const float*)d_in[1];
        pat = (const float*)d_in[0];
    }
    float* out = (float*)d_out;

    const int scan_smem = C_ * 1024 * (int)sizeof(float);   // 64 KB dynamic
    cudaFuncSetAttribute(scan_kernel,
                         cudaFuncAttributeMaxDynamicSharedMemorySize, scan_smem);

    cudaMemsetAsync(d_out, 0, (size_t)out_size * sizeof(float), 0);
    xstats_kernel<<<B_ * NCH_, 256>>>(x);
    qk_kernel<<<B_ * 64, 256>>>(x, pat, 0, 0, 1);

    for (int c = 0; c < NCH_; c++) {
        scan_kernel<<<B_, 1024, scan_smem>>>(c);
        apply_kernel<<<B_ * 8, 256>>>(x, pat, out, c);
        if (c + 1 < NCH_)
            qk_kernel<<<B_ * 64, 256>>>(x, pat, (c + 1) * C_, (c + 1) & 1, 0);
    }
}